// round 6
// baseline (speedup 1.0000x reference)
#include <cuda_runtime.h>
#include <cuda_bf16.h>
#include <cstdint>

#define BATCH  64
#define SEQ    512
#define INDIM  512
#define HID    1024
#define OUTDIM 512

// ---------------- device scratch ---------------------------------------------
__device__ float          g_xp[(size_t)BATCH * SEQ * HID];     // 128 MB x-projection
__device__ __nv_bfloat16  g_xhi[(size_t)BATCH * SEQ * INDIM];  // X split hi
__device__ __nv_bfloat16  g_xlo[(size_t)BATCH * SEQ * INDIM];  // X split lo
__device__ __nv_bfloat16  g_wihhi[(size_t)HID * INDIM];        // W_ih hi
__device__ __nv_bfloat16  g_wihlo[(size_t)HID * INDIM];        // W_ih lo
__device__ float          g_bias[HID];                         // b_ih + b_hh
__device__ __nv_bfloat16  g_whi[(size_t)HID * HID];            // W_hh hi
__device__ __nv_bfloat16  g_wlo[(size_t)HID * HID];            // W_hh lo
__device__ unsigned       g_sig[4][32];                        // per-bg counters (padded)

// hidden state in bulk-copy-ready padded layout:
// [parity 2][bg 4][comp 2][row 16][2064 B] (1032 bf16/row, 1024 used)
#define HP_PAR   264192u
#define HP_BG    66048u
#define HP_COMP  33024u
#define HP_ROW   2064u
#define HP_SLICE 8256u                  // HP_BG / 8 cluster ranks
__device__ __align__(16) unsigned char g_hpk[2 * 4 * HP_BG];

// ---------------- mma / ldmatrix helpers -------------------------------------
__device__ __forceinline__ void ldsm4(uint32_t &r0, uint32_t &r1, uint32_t &r2,
                                      uint32_t &r3, uint32_t addr) {
    asm volatile("ldmatrix.sync.aligned.m8n8.x4.shared.b16 {%0,%1,%2,%3}, [%4];"
                 : "=r"(r0), "=r"(r1), "=r"(r2), "=r"(r3) : "r"(addr));
}
__device__ __forceinline__ void mma16816(float* d, uint32_t a0, uint32_t a1,
                                         uint32_t a2, uint32_t a3,
                                         uint32_t b0, uint32_t b1) {
    asm volatile(
        "mma.sync.aligned.m16n8k16.row.col.f32.bf16.bf16.f32 "
        "{%0,%1,%2,%3},{%4,%5,%6,%7},{%8,%9},{%0,%1,%2,%3};"
        : "+f"(d[0]), "+f"(d[1]), "+f"(d[2]), "+f"(d[3])
        : "r"(a0), "r"(a1), "r"(a2), "r"(a3), "r"(b0), "r"(b1));
}
__device__ __forceinline__ void split_bf16(float v, __nv_bfloat16 &hi, __nv_bfloat16 &lo) {
    hi = __float2bfloat16(v);
    lo = __float2bfloat16(v - __bfloat162float(hi));
}

// ---------------- init: zero hidden buffers + signals ------------------------
__global__ void k_init() {
    int i = blockIdx.x * blockDim.x + threadIdx.x;    // 133120 threads
    if (i < 128) ((unsigned*)g_sig)[i] = 0u;
    if (i < 132096) ((uint32_t*)g_hpk)[i] = 0u;
}

// ---------------- prep: split X, W_hh, W_ih; fold biases ---------------------
__global__ void k_prep(const float* __restrict__ X, const float* __restrict__ Whh,
                       const float* __restrict__ Wih, const float* __restrict__ bih,
                       const float* __restrict__ bhh) {
    int i = blockIdx.x * blockDim.x + threadIdx.x;    // 16777216 threads
    {
        __nv_bfloat16 hi, lo;
        split_bf16(X[i], hi, lo);
        g_xhi[i] = hi; g_xlo[i] = lo;
    }
    if (i < HID * HID) {
        __nv_bfloat16 hi, lo;
        split_bf16(Whh[i], hi, lo);
        g_whi[i] = hi; g_wlo[i] = lo;
    }
    if (i < HID * INDIM) {
        __nv_bfloat16 hi, lo;
        split_bf16(Wih[i], hi, lo);
        g_wihhi[i] = hi; g_wihlo[i] = lo;
    }
    if (i < HID) g_bias[i] = bih[i] + bhh[i];
}

// ---------------- x_proj tensor-core GEMM ------------------------------------
#define XROW     144
#define XA_COMP  (128 * XROW)
#define XA_STAGE (2 * XA_COMP)
#define XB_COMP  (64 * XROW)
#define XB_STAGE (2 * XB_COMP)
#define XS_A     0
#define XS_B     (2 * XA_STAGE)
#define XS_BYTES (XS_B + 2 * XB_STAGE)

__device__ __forceinline__ void xp_stage(uint32_t smb, int s, int kt,
                                         int m0, int n0, int tid) {
    const int kb = kt * 64;
#pragma unroll
    for (int r = 0; r < 8; r++) {
        int q = tid + 256 * r;
        int c = q >> 10, row = (q >> 3) & 127, kg = q & 7;
        const __nv_bfloat16* src =
            (c ? g_xlo : g_xhi) + (size_t)(m0 + row) * INDIM + kb + kg * 8;
        uint32_t dst = smb + XS_A + s * XA_STAGE + c * XA_COMP + row * XROW + kg * 16;
        asm volatile("cp.async.cg.shared.global [%0], [%1], 16;" :: "r"(dst), "l"(src));
    }
#pragma unroll
    for (int r = 0; r < 4; r++) {
        int q = tid + 256 * r;
        int c = q >> 9, row = (q >> 3) & 63, kg = q & 7;
        const __nv_bfloat16* src =
            (c ? g_wihlo : g_wihhi) + (size_t)(n0 + row) * INDIM + kb + kg * 8;
        uint32_t dst = smb + XS_B + s * XB_STAGE + c * XB_COMP + row * XROW + kg * 16;
        asm volatile("cp.async.cg.shared.global [%0], [%1], 16;" :: "r"(dst), "l"(src));
    }
}

__global__ __launch_bounds__(256) void k_xproj()
{
    extern __shared__ char smc[];
    const uint32_t smb = (uint32_t)__cvta_generic_to_shared(smc);

    const int tid  = threadIdx.x;
    const int lane = tid & 31;
    const int w    = tid >> 5;
    const int wm   = (w >> 1) * 32;
    const int wn   = (w & 1) * 32;
    const int m0   = blockIdx.x * 128;
    const int n0   = blockIdx.y * 64;

    float D1[2][4][4], D2[2][4][4];
#pragma unroll
    for (int i = 0; i < 2; i++)
#pragma unroll
        for (int j = 0; j < 4; j++)
#pragma unroll
            for (int r = 0; r < 4; r++) { D1[i][j][r] = 0.f; D2[i][j][r] = 0.f; }

    const uint32_t aoff = (wm + (lane & 15)) * XROW + (lane >> 4) * 16;
    const uint32_t boff = (wn + (lane & 7) + ((lane >> 4) << 3)) * XROW
                        + ((lane >> 3) & 1) * 16;

    xp_stage(smb, 0, 0, m0, n0, tid);
    asm volatile("cp.async.commit_group;");

    for (int kt = 0; kt < INDIM / 64; kt++) {
        const int s = kt & 1;
        if (kt + 1 < INDIM / 64) {
            xp_stage(smb, s ^ 1, kt + 1, m0, n0, tid);
            asm volatile("cp.async.commit_group;");
            asm volatile("cp.async.wait_group 1;");
        } else {
            asm volatile("cp.async.wait_group 0;");
        }
        __syncthreads();

        const uint32_t ah_b = smb + XS_A + s * XA_STAGE + aoff;
        const uint32_t al_b = ah_b + XA_COMP;
        const uint32_t bh_b = smb + XS_B + s * XB_STAGE + boff;
        const uint32_t bl_b = bh_b + XB_COMP;

#pragma unroll
        for (int ks = 0; ks < 4; ks++) {
            const uint32_t ka = ks * 32;
            uint32_t ah[2][4], al[2][4], bh[2][4], bl[2][4];
            ldsm4(ah[0][0], ah[0][1], ah[0][2], ah[0][3], ah_b + ka);
            ldsm4(ah[1][0], ah[1][1], ah[1][2], ah[1][3], ah_b + 16 * XROW + ka);
            ldsm4(al[0][0], al[0][1], al[0][2], al[0][3], al_b + ka);
            ldsm4(al[1][0], al[1][1], al[1][2], al[1][3], al_b + 16 * XROW + ka);
            ldsm4(bh[0][0], bh[0][1], bh[0][2], bh[0][3], bh_b + ka);
            ldsm4(bh[1][0], bh[1][1], bh[1][2], bh[1][3], bh_b + 16 * XROW + ka);
            ldsm4(bl[0][0], bl[0][1], bl[0][2], bl[0][3], bl_b + ka);
            ldsm4(bl[1][0], bl[1][1], bl[1][2], bl[1][3], bl_b + 16 * XROW + ka);
#pragma unroll
            for (int mi = 0; mi < 2; mi++)
#pragma unroll
                for (int tt = 0; tt < 4; tt++) {
                    int h2 = tt >> 1, p = (tt & 1) * 2;
                    mma16816(D1[mi][tt], ah[mi][0], ah[mi][1], ah[mi][2], ah[mi][3],
                             bh[h2][p], bh[h2][p + 1]);
                    mma16816(D2[mi][tt], al[mi][0], al[mi][1], al[mi][2], al[mi][3],
                             bh[h2][p], bh[h2][p + 1]);
                    mma16816(D2[mi][tt], ah[mi][0], ah[mi][1], ah[mi][2], ah[mi][3],
                             bl[h2][p], bl[h2][p + 1]);
                }
        }
        __syncthreads();
    }

    const int rbase = lane >> 2;
    const int cbase = 2 * (lane & 3);
#pragma unroll
    for (int mi = 0; mi < 2; mi++)
#pragma unroll
        for (int tt = 0; tt < 4; tt++) {
            int gm = m0 + wm + mi * 16 + rbase;
            int gn = n0 + wn + tt * 8 + cbase;
            float2 b2 = *(const float2*)&g_bias[gn];
            float2 v;
            v.x = D1[mi][tt][0] + D2[mi][tt][0] + b2.x;
            v.y = D1[mi][tt][1] + D2[mi][tt][1] + b2.y;
            *(float2*)(g_xp + (size_t)gm * HID + gn) = v;
            v.x = D1[mi][tt][2] + D2[mi][tt][2] + b2.x;
            v.y = D1[mi][tt][3] + D2[mi][tt][3] + b2.y;
            *(float2*)(g_xp + (size_t)(gm + 8) * HID + gn) = v;
        }
}

// ---------------- recurrence: persistent cluster-multicast kernel ------------
// 128 CTAs x 256 thr, clusters of 8 (same bg chain). W_hh frags in registers.
// h exchange: global padded image -> cluster bulk multicast (1/8 slice each).
#define R_CTAS    128
#define R_THREADS 256

#define SM_HB    0                       // W stage (once), then hbuf[2][66048]
#define SM_RED   132096                  // [8][528] f32
#define RED_ROW  528
#define SM_MBAR  148992                  // 2 mbarriers
#define SM_BYTES 149504

__global__ __launch_bounds__(R_THREADS, 1) __cluster_dims__(8, 1, 1) void k_recur()
{
    extern __shared__ char smc[];
    const uint32_t smb = (uint32_t)__cvta_generic_to_shared(smc);
    float* redf = (float*)(smc + SM_RED);

    const int tid  = threadIdx.x;
    const int lane = tid & 31;
    const int w    = tid >> 5;
    const int jg   = blockIdx.x & 31;
    const int bgi  = blockIdx.x >> 5;
    const int cta_j0 = jg * 32;
    uint32_t rank;
    asm("mov.u32 %0, %%cluster_ctarank;" : "=r"(rank));

    unsigned* my_sig = &g_sig[bgi][0];

    // ---- stage W slice (32j x 1024k, hi+lo) into smem (region reused later) --
#pragma unroll 8
    for (int it = 0; it < 32; it++) {
        int q = tid + R_THREADS * it;
        int comp = q >> 12, row = (q >> 7) & 31, g = q & 127;
        const __nv_bfloat16* src =
            (comp ? g_wlo : g_whi) + (size_t)(cta_j0 + row) * HID + g * 8;
        *(uint4*)(smc + comp * 66048 + row * 2064 + g * 16) = *(const uint4*)src;
    }
    __syncthreads();

    uint32_t b_base[2][2];
#pragma unroll
    for (int comp = 0; comp < 2; comp++)
#pragma unroll
        for (int half = 0; half < 2; half++)
            b_base[comp][half] = smb + comp * 66048
                + (half * 16 + (lane >> 4) * 8 + (lane & 7)) * 2064
                + ((lane >> 3) & 1) * 16;

    const int koffw = w * 128;

    // ---- hoist all W fragments into registers --------------------------------
    uint32_t wf[2][4][2][2][4];    // [chunk][ks][comp][half][reg]
#pragma unroll
    for (int c = 0; c < 2; c++)
#pragma unroll
        for (int ks = 0; ks < 4; ks++)
#pragma unroll
            for (int comp = 0; comp < 2; comp++)
#pragma unroll
                for (int half = 0; half < 2; half++)
                    ldsm4(wf[c][ks][comp][half][0], wf[c][ks][comp][half][1],
                          wf[c][ks][comp][half][2], wf[c][ks][comp][half][3],
                          b_base[comp][half] + c * 1024 + koffw + ks * 32);

    // ---- init mbarriers, cluster-wide visibility -----------------------------
    if (tid == 0) {
        asm volatile("mbarrier.init.shared.b64 [%0], %1;"
                     :: "r"(smb + SM_MBAR), "r"(1u) : "memory");
        asm volatile("mbarrier.init.shared.b64 [%0], %1;"
                     :: "r"(smb + SM_MBAR + 8), "r"(1u) : "memory");
        asm volatile("fence.proxy.async;" ::: "memory");
    }
    asm volatile("barrier.cluster.arrive.aligned;" ::: "memory");
    asm volatile("barrier.cluster.wait.aligned;" ::: "memory");

    // A-fragment ldmatrix bases (comp-relative; add parity + chunk offsets)
    uint32_t a_base[2];
#pragma unroll
    for (int comp = 0; comp < 2; comp++)
        a_base[comp] = smb + SM_HB + comp * HP_COMP
                     + (lane & 15) * HP_ROW + (lane >> 4) * 16;

    const int o0 = tid * 2;
    const int bl = o0 >> 5, jl = o0 & 31;

    for (int t = 0; t < SEQ; t++) {
        const uint32_t par  = (t & 1) * HP_BG;
        const uint32_t mbar = smb + SM_MBAR + (t & 1) * 8;
        const unsigned phase = (unsigned)(t >> 1) & 1u;

        float2 xp = __ldg((const float2*)
            (g_xp + ((size_t)(bgi * 16 + bl) * SEQ + t) * HID + cta_j0 + jl));

        if (tid == 0) {
            if (t) {
                const unsigned need = 32u * (unsigned)t;
                unsigned v;
                do {
                    asm volatile("ld.acquire.gpu.global.u32 %0, [%1];"
                                 : "=r"(v) : "l"(my_sig));
                } while (v < need);
            }
            asm volatile("fence.proxy.async;" ::: "memory");
            asm volatile("mbarrier.arrive.expect_tx.shared.b64 _, [%0], %1;"
                         :: "r"(mbar), "r"(HP_BG) : "memory");
            const unsigned char* src =
                g_hpk + (t & 1) * HP_PAR + bgi * HP_BG + rank * HP_SLICE;
            asm volatile(
                "cp.async.bulk.shared::cluster.global.mbarrier::complete_tx::bytes"
                ".multicast::cluster [%0], [%1], %2, [%3], %4;"
                :: "r"(smb + SM_HB + par + rank * HP_SLICE), "l"(src),
                   "r"(HP_SLICE), "r"(mbar), "h"((unsigned short)0xFF)
                : "memory");
        }

        // all threads wait for the full 66048-byte slice
        {
            uint32_t done;
            asm volatile(
                "{\n\t.reg .pred p;\n\t"
                "mbarrier.try_wait.parity.acquire.cta.shared::cta.b64 p, [%1], %2;\n\t"
                "selp.b32 %0, 1, 0, p;\n\t}"
                : "=r"(done) : "r"(mbar), "r"(phase) : "memory");
            if (!done) {
                asm volatile(
                    "{\n\t.reg .pred P1;\n\t"
                    "W%=:\n\t"
                    "mbarrier.try_wait.parity.acquire.cta.shared::cta.b64 P1, [%0], %1, 0x989680;\n\t"
                    "@P1 bra.uni D%=;\n\t"
                    "bra.uni W%=;\n\t"
                    "D%=:\n\t}"
                    :: "r"(mbar), "r"(phase) : "memory");
            }
        }

        float D1[4][4], D2[4][4];
#pragma unroll
        for (int i = 0; i < 4; i++)
#pragma unroll
            for (int j = 0; j < 4; j++) { D1[i][j] = 0.f; D2[i][j] = 0.f; }

#pragma unroll
        for (int c = 0; c < 2; c++) {
#pragma unroll
            for (int ks = 0; ks < 4; ks++) {
                const uint32_t ka = par + c * 1024 + koffw + ks * 32;
                uint32_t ah[4], al[4];
                ldsm4(ah[0], ah[1], ah[2], ah[3], a_base[0] + ka);
                ldsm4(al[0], al[1], al[2], al[3], a_base[1] + ka);
#pragma unroll
                for (int tt = 0; tt < 4; tt++) {
                    int h2 = tt >> 1, p = (tt & 1) * 2;
                    mma16816(D1[tt], ah[0], ah[1], ah[2], ah[3],
                             wf[c][ks][0][h2][p], wf[c][ks][0][h2][p + 1]);
                }
#pragma unroll
                for (int tt = 0; tt < 4; tt++) {
                    int h2 = tt >> 1, p = (tt & 1) * 2;
                    mma16816(D2[tt], al[0], al[1], al[2], al[3],
                             wf[c][ks][0][h2][p], wf[c][ks][0][h2][p + 1]);
                }
#pragma unroll
                for (int tt = 0; tt < 4; tt++) {
                    int h2 = tt >> 1, p = (tt & 1) * 2;
                    mma16816(D2[tt], ah[0], ah[1], ah[2], ah[3],
                             wf[c][ks][1][h2][p], wf[c][ks][1][h2][p + 1]);
                }
            }
        }

        // ---- cross-warp k reduction via smem ----
#pragma unroll
        for (int tt = 0; tt < 4; tt++)
#pragma unroll
            for (int r = 0; r < 4; r++) {
                int b = (lane >> 2) + ((r >= 2) ? 8 : 0);
                int j = tt * 8 + 2 * (lane & 3) + (r & 1);
                redf[w * RED_ROW + b * 33 + j] = D1[tt][r] + D2[tt][r];
            }
        __syncthreads();

        float v0 = 0.f, v1 = 0.f;
#pragma unroll
        for (int ww = 0; ww < 8; ww++) {
            v0 += redf[ww * RED_ROW + bl * 33 + jl];
            v1 += redf[ww * RED_ROW + bl * 33 + jl + 1];
        }
        v0 = tanhf(v0 + xp.x);
        v1 = tanhf(v1 + xp.y);

        __nv_bfloat16 h0, l0, h1, l1;
        split_bf16(v0, h0, l0);
        split_bf16(v1, h1, l1);
        unsigned char* hb = g_hpk + ((t + 1) & 1) * HP_PAR + bgi * HP_BG;
        const uint32_t off = bl * HP_ROW + (cta_j0 + jl) * 2;
        __nv_bfloat162 ph; ph.x = h0; ph.y = h1;
        __nv_bfloat162 pl; pl.x = l0; pl.y = l1;
        *(__nv_bfloat162*)(hb + off)           = ph;
        *(__nv_bfloat162*)(hb + HP_COMP + off) = pl;

        __syncthreads();
        if (tid == 0)
            asm volatile("red.release.gpu.global.add.u32 [%0], %1;"
                         :: "l"(my_sig), "r"(1u));
    }

    // no CTA may exit while peer multicasts can target its smem
    asm volatile("barrier.cluster.arrive.aligned;" ::: "memory");
    asm volatile("barrier.cluster.wait.aligned;" ::: "memory");
}

// ---------------- output projection ------------------------------------------
__global__ __launch_bounds__(256) void k_out(
    const float* __restrict__ Who, const float* __restrict__ bho,
    float* __restrict__ out)
{
    const int lane = threadIdx.x & 31;
    const int gw   = blockIdx.x * 8 + (threadIdx.x >> 5);
    const int o0   = (gw >> 3) * 2;
    const int b0   = (gw & 7) * 8;

    const float4* W0 = (const float4*)(Who + (size_t)o0 * HID);
    const float4* W1 = (const float4*)(Who + (size_t)(o0 + 1) * HID);
    float4 wr0[8], wr1[8];
#pragma unroll
    for (int i = 0; i < 8; i++) {
        wr0[i] = W0[i * 32 + lane];
        wr1[i] = W1[i * 32 + lane];
    }
    float bias0 = __ldg(&bho[o0]), bias1 = __ldg(&bho[o0 + 1]);

#pragma unroll
    for (int b = 0; b < 8; b++) {
        const int bb = b0 + b;
        // final h (after step 511) lives in parity 0 of the packed image
        const unsigned char* hb = g_hpk + (bb >> 4) * HP_BG + (bb & 15) * HP_ROW;
        float a0 = 0.f, a1 = 0.f;
#pragma unroll
        for (int i = 0; i < 8; i++) {
            int k0 = lane * 4 + i * 128;
            __nv_bfloat162 ph0 = *(const __nv_bfloat162*)(hb + k0 * 2);
            __nv_bfloat162 ph1 = *(const __nv_bfloat162*)(hb + k0 * 2 + 4);
            __nv_bfloat162 pl0 = *(const __nv_bfloat162*)(hb + HP_COMP + k0 * 2);
            __nv_bfloat162 pl1 = *(const __nv_bfloat162*)(hb + HP_COMP + k0 * 2 + 4);
            float2 f0 = __bfloat1622float2(ph0), g0 = __bfloat1622float2(pl0);
            float2 f1 = __bfloat1622float2(ph1), g1 = __bfloat1622float2(pl1);
            float hx = f0.x + g0.x, hy = f0.y + g0.y;
            float hz = f1.x + g1.x, hw = f1.y + g1.y;
            a0 += hx * wr0[i].x + hy * wr0[i].y + hz * wr0[i].z + hw * wr0[i].w;
            a1 += hx * wr1[i].x + hy * wr1[i].y + hz * wr1[i].z + hw * wr1[i].w;
        }
#pragma unroll
        for (int off = 16; off; off >>= 1) {
            a0 += __shfl_xor_sync(0xffffffffu, a0, off);
            a1 += __shfl_xor_sync(0xffffffffu, a1, off);
        }
        if (lane == 0) {
            out[(size_t)bb * OUTDIM + o0]     = a0 + bias0;
            out[(size_t)bb * OUTDIM + o0 + 1] = a1 + bias1;
        }
    }
}

// ---------------- launch ------------------------------------------------------
extern "C" void kernel_launch(void* const* d_in, const int* in_sizes, int n_in,
                              void* d_out, int out_size)
{
    (void)in_sizes; (void)n_in; (void)out_size;
    const float* X   = (const float*)d_in[0];
    const float* Wih = (const float*)d_in[1];
    const float* bih = (const float*)d_in[2];
    const float* Whh = (const float*)d_in[3];
    const float* bhh = (const float*)d_in[4];
    const float* Who = (const float*)d_in[5];
    const float* bho = (const float*)d_in[6];
    float* out = (float*)d_out;

    cudaFuncSetAttribute(k_xproj, cudaFuncAttributeMaxDynamicSharedMemorySize,
                         XS_BYTES);
    cudaFuncSetAttribute(k_recur, cudaFuncAttributeMaxDynamicSharedMemorySize,
                         SM_BYTES);

    k_init<<<520, 256>>>();
    k_prep<<<65536, 256>>>(X, Whh, Wih, bih, bhh);
    dim3 xg(BATCH * SEQ / 128, HID / 64);
    k_xproj<<<xg, 256, XS_BYTES>>>();
    k_recur<<<R_CTAS, R_THREADS, SM_BYTES>>>();
    k_out<<<256, 256>>>(Who, bho, out);
}